// round 1
// baseline (speedup 1.0000x reference)
#include <cuda_runtime.h>
#include <math.h>

#define Bb   8
#define Nn   2048
#define FIN  256
#define FOUT 128

// Scratch (device globals: allocation-free rule)
__device__ float g_Wh[Bb * Nn * FOUT];
__device__ float g_f1[Bb * Nn];
__device__ float g_f2[Bb * Nn];

typedef unsigned long long u64;

__forceinline__ __device__ u64 pk2(float lo, float hi) {
    u64 r;
    asm("mov.b64 %0, {%1, %2};" : "=l"(r) : "f"(lo), "f"(hi));
    return r;
}
__forceinline__ __device__ void upk2(u64 v, float &lo, float &hi) {
    asm("mov.b64 {%0, %1}, %2;" : "=f"(lo), "=f"(hi) : "l"(v));
}
__forceinline__ __device__ void fma2(u64 &d, u64 a, u64 b) {
    asm("fma.rn.f32x2 %0, %1, %2, %3;" : "=l"(d) : "l"(a), "l"(b), "l"(d));
}

// ============================================================
// Kernel 1: Wh = x @ W   (per batch: [2048,256] @ [256,128])
// BM=64, BN=128 (full Fout), BK=32, 256 threads, thread tile 4x8
// ============================================================
__global__ __launch_bounds__(256) void gat_gemm_wh(
    const float* __restrict__ x, const float* __restrict__ W)
{
    __shared__ __align__(16) float xs[64][32];
    __shared__ __align__(16) float ws[32][FOUT];

    const int t  = threadIdx.x;
    const int b  = blockIdx.y;
    const int i0 = blockIdx.x * 64;
    const int tr = t >> 4;        // 0..15 -> rows tr*4 .. tr*4+3
    const int tc = t & 15;        // cols: [tc*4 .. +3] and [64+tc*4 .. +3]
    const int r0 = tr * 4;
    const int c0a = tc * 4;
    const int c0b = 64 + tc * 4;

    u64 acc[4][4];                 // [row][pair]: pairs 0,1 = seg a; 2,3 = seg b
    #pragma unroll
    for (int i = 0; i < 4; i++)
        #pragma unroll
        for (int j = 0; j < 4; j++) acc[i][j] = pk2(0.f, 0.f);

    const float* xb = x + ((size_t)b * Nn + i0) * FIN;

    for (int k0 = 0; k0 < FIN; k0 += 32) {
        __syncthreads();
        // load x tile 64x32 (2 float4 per thread), rows contiguous in k
        #pragma unroll
        for (int v = 0; v < 2; v++) {
            int flat = t + 256 * v;
            int row  = flat >> 3;
            int kq   = (flat & 7) * 4;
            *(float4*)&xs[row][kq] = *(const float4*)&xb[(size_t)row * FIN + k0 + kq];
        }
        // load W tile 32x128 (4 float4 per thread)
        #pragma unroll
        for (int v = 0; v < 4; v++) {
            int flat = t + 256 * v;
            int kr   = flat >> 5;
            int cq   = (flat & 31) * 4;
            *(float4*)&ws[kr][cq] = *(const float4*)&W[(size_t)(k0 + kr) * FOUT + cq];
        }
        __syncthreads();

        #pragma unroll
        for (int kk = 0; kk < 32; kk++) {
            float4 wa = *(float4*)&ws[kk][c0a];
            float4 wb = *(float4*)&ws[kk][c0b];
            u64 bw0 = pk2(wa.x, wa.y), bw1 = pk2(wa.z, wa.w);
            u64 bw2 = pk2(wb.x, wb.y), bw3 = pk2(wb.z, wb.w);
            #pragma unroll
            for (int ri = 0; ri < 4; ri++) {
                float av = xs[r0 + ri][kk];
                u64 ap = pk2(av, av);
                fma2(acc[ri][0], ap, bw0);
                fma2(acc[ri][1], ap, bw1);
                fma2(acc[ri][2], ap, bw2);
                fma2(acc[ri][3], ap, bw3);
            }
        }
    }

    float* whb = g_Wh + ((size_t)b * Nn + i0) * FOUT;
    #pragma unroll
    for (int ri = 0; ri < 4; ri++) {
        float4 oa, ob;
        upk2(acc[ri][0], oa.x, oa.y); upk2(acc[ri][1], oa.z, oa.w);
        upk2(acc[ri][2], ob.x, ob.y); upk2(acc[ri][3], ob.z, ob.w);
        *(float4*)&whb[(size_t)(r0 + ri) * FOUT + c0a] = oa;
        *(float4*)&whb[(size_t)(r0 + ri) * FOUT + c0b] = ob;
    }
}

// ============================================================
// Kernel 2: f1[row] = Wh[row,:].a1 ; f2[row] = Wh[row,:].a2
// one row per 128-thread block
// ============================================================
__global__ __launch_bounds__(128) void gat_calc_f(const float* __restrict__ a)
{
    const int row = blockIdx.x;
    const int t   = threadIdx.x;
    float wh = g_Wh[(size_t)row * FOUT + t];
    float p1 = wh * a[t];
    float p2 = wh * a[FOUT + t];
    #pragma unroll
    for (int o = 16; o > 0; o >>= 1) {
        p1 += __shfl_xor_sync(0xffffffffu, p1, o);
        p2 += __shfl_xor_sync(0xffffffffu, p2, o);
    }
    __shared__ float s1[4], s2[4];
    if ((t & 31) == 0) { s1[t >> 5] = p1; s2[t >> 5] = p2; }
    __syncthreads();
    if (t == 0) {
        g_f1[row] = s1[0] + s1[1] + s1[2] + s1[3];
        g_f2[row] = s2[0] + s2[1] + s2[2] + s2[3];
    }
}

// ============================================================
// Kernel 3: fused masked-leaky-softmax attention + P@Wh + ELU-out
// Block: 32 query rows x full Fout=128, 256 threads.
// Col loop over N in tiles of 32. No max-tracking (exp can't overflow:
// |e| < ~40 sigma away from 88).
// ============================================================
__global__ __launch_bounds__(256) void gat_attn(
    const int* __restrict__ adj, float* __restrict__ out)
{
    __shared__ __align__(16) float Whs[32][FOUT];
    __shared__ float Ps[32][33];   // +1 pad: kill row-stride bank conflicts
    __shared__ float f1s[32];
    __shared__ float f2s[32];
    __shared__ float rowsum_s[32];

    const int t  = threadIdx.x;
    const int b  = blockIdx.y;
    const int i0 = blockIdx.x * 32;

    // PV mapping: 2 rows x 8 cols per thread
    const int tr  = t >> 4;            // 0..15
    const int tc  = t & 15;
    const int r0  = tr * 2;
    const int c0a = tc * 4;
    const int c0b = 64 + tc * 4;

    // P mapping: rows rps+8k (k=0..3), col jp; one warp = one rps
    const int rps = t >> 5;            // 0..7
    const int jp  = t & 31;

    if (t < 32) f1s[t] = g_f1[(size_t)b * Nn + i0 + t];

    u64 acc[2][4];
    #pragma unroll
    for (int i = 0; i < 2; i++)
        #pragma unroll
        for (int j = 0; j < 4; j++) acc[i][j] = pk2(0.f, 0.f);

    float sum_acc[4] = {0.f, 0.f, 0.f, 0.f};

    const float* whb = g_Wh + (size_t)b * Nn * FOUT;
    const int*   adjb = adj + (size_t)b * Nn * Nn;

    for (int jt = 0; jt < 64; jt++) {
        const int j0 = jt * 32;

        // prefetch adj (independent of smem) before barrier
        int av[4];
        #pragma unroll
        for (int k = 0; k < 4; k++)
            av[k] = adjb[(size_t)(i0 + rps + 8 * k) * Nn + j0 + jp];

        __syncthreads();   // previous PV done with Whs/Ps

        // stage Wh tile [32][128]
        #pragma unroll
        for (int v = 0; v < 4; v++) {
            int flat = t + 256 * v;
            int jr   = flat >> 5;
            int cq   = (flat & 31) * 4;
            *(float4*)&Whs[jr][cq] = *(const float4*)&whb[(size_t)(j0 + jr) * FOUT + cq];
        }
        if (t < 32) f2s[t] = g_f2[(size_t)b * Nn + j0 + t];
        __syncthreads();

        // P tile: leaky -> mask -> exp (no max shift needed)
        #pragma unroll
        for (int k = 0; k < 4; k++) {
            int r = rps + 8 * k;
            float e = f1s[r] + f2s[jp];
            e = (e < 0.f) ? 2.0f * e : e;          // ALPHA = 2.0
            float p = (av[k] > 0) ? __expf(e) : 0.f;
            Ps[r][jp] = p;
            sum_acc[k] += p;
        }
        __syncthreads();

        // PV accumulate with packed f32x2 FMA
        #pragma unroll 8
        for (int j = 0; j < 32; j++) {
            float p0 = Ps[r0][j];
            float p1 = Ps[r0 + 1][j];
            u64 pp0 = pk2(p0, p0);
            u64 pp1 = pk2(p1, p1);
            float4 wa = *(float4*)&Whs[j][c0a];
            float4 wb = *(float4*)&Whs[j][c0b];
            u64 w0 = pk2(wa.x, wa.y), w1 = pk2(wa.z, wa.w);
            u64 w2 = pk2(wb.x, wb.y), w3 = pk2(wb.z, wb.w);
            fma2(acc[0][0], pp0, w0); fma2(acc[0][1], pp0, w1);
            fma2(acc[0][2], pp0, w2); fma2(acc[0][3], pp0, w3);
            fma2(acc[1][0], pp1, w0); fma2(acc[1][1], pp1, w1);
            fma2(acc[1][2], pp1, w2); fma2(acc[1][3], pp1, w3);
        }
    }

    // softmax denominators: lanes of warp rps share rows {rps+8k}
    #pragma unroll
    for (int k = 0; k < 4; k++) {
        float s = sum_acc[k];
        #pragma unroll
        for (int o = 16; o > 0; o >>= 1)
            s += __shfl_xor_sync(0xffffffffu, s, o);
        if (jp == 0) rowsum_s[rps + 8 * k] = s;
    }
    __syncthreads();

    const float inv0 = 1.0f / rowsum_s[r0];
    const float inv1 = 1.0f / rowsum_s[r0 + 1];
    float* ob = out + ((size_t)b * Nn + i0) * FOUT;

    #pragma unroll
    for (int ri = 0; ri < 2; ri++) {
        float inv = (ri == 0) ? inv0 : inv1;
        float v[8];
        upk2(acc[ri][0], v[0], v[1]); upk2(acc[ri][1], v[2], v[3]);
        upk2(acc[ri][2], v[4], v[5]); upk2(acc[ri][3], v[6], v[7]);
        #pragma unroll
        for (int i = 0; i < 8; i++) {
            float h = v[i] * inv;
            v[i] = (h > 0.f) ? h : expm1f(h);      // matches jnp.expm1 path
        }
        float4 oa = make_float4(v[0], v[1], v[2], v[3]);
        float4 obv = make_float4(v[4], v[5], v[6], v[7]);
        *(float4*)&ob[(size_t)(r0 + ri) * FOUT + c0a] = oa;
        *(float4*)&ob[(size_t)(r0 + ri) * FOUT + c0b] = obv;
    }
}

// ============================================================
extern "C" void kernel_launch(void* const* d_in, const int* in_sizes, int n_in,
                              void* d_out, int out_size)
{
    const float* x   = (const float*)d_in[0];   // [8,2048,256] f32
    const int*   adj = (const int*)  d_in[1];   // [8,2048,2048] i32
    const float* W   = (const float*)d_in[2];   // [256,128] f32
    const float* a   = (const float*)d_in[3];   // [256,1] f32
    float*       out = (float*)d_out;           // [8,2048,128] f32

    dim3 g1(Nn / 64, Bb);
    gat_gemm_wh<<<g1, 256>>>(x, W);

    gat_calc_f<<<Bb * Nn, 128>>>(a);

    dim3 g3(Nn / 32, Bb);
    gat_attn<<<g3, 256>>>(adj, out);
}

// round 2
// speedup vs baseline: 1.2624x; 1.2624x over previous
#include <cuda_runtime.h>
#include <math.h>

#define Bb   8
#define Nn   2048
#define FIN  256
#define FOUT 128

// Scratch (device globals: allocation-free rule)
__device__ float g_Wh[Bb * Nn * FOUT];
__device__ float g_f1[Bb * Nn];
__device__ float g_f2[Bb * Nn];

typedef unsigned long long u64;

__forceinline__ __device__ u64 pk2(float lo, float hi) {
    u64 r;
    asm("mov.b64 %0, {%1, %2};" : "=l"(r) : "f"(lo), "f"(hi));
    return r;
}
__forceinline__ __device__ void upk2(u64 v, float &lo, float &hi) {
    asm("mov.b64 {%0, %1}, %2;" : "=f"(lo), "=f"(hi) : "l"(v));
}
__forceinline__ __device__ void fma2(u64 &d, u64 a, u64 b) {
    asm("fma.rn.f32x2 %0, %1, %2, %3;" : "=l"(d) : "l"(a), "l"(b), "l"(d));
}

// ============================================================
// Kernel 1: Wh = x @ W   (per batch: [2048,256] @ [256,128])
// BM=64, BN=128 (full Fout), BK=32, 256 threads, thread tile 4x8
// ============================================================
__global__ __launch_bounds__(256) void gat_gemm_wh(
    const float* __restrict__ x, const float* __restrict__ W)
{
    __shared__ __align__(16) float xs[64][32];
    __shared__ __align__(16) float ws[32][FOUT];

    const int t  = threadIdx.x;
    const int b  = blockIdx.y;
    const int i0 = blockIdx.x * 64;
    const int tr = t >> 4;
    const int tc = t & 15;
    const int r0 = tr * 4;
    const int c0a = tc * 4;
    const int c0b = 64 + tc * 4;

    u64 acc[4][4];
    #pragma unroll
    for (int i = 0; i < 4; i++)
        #pragma unroll
        for (int j = 0; j < 4; j++) acc[i][j] = pk2(0.f, 0.f);

    const float* xb = x + ((size_t)b * Nn + i0) * FIN;

    for (int k0 = 0; k0 < FIN; k0 += 32) {
        __syncthreads();
        #pragma unroll
        for (int v = 0; v < 2; v++) {
            int flat = t + 256 * v;
            int row  = flat >> 3;
            int kq   = (flat & 7) * 4;
            *(float4*)&xs[row][kq] = *(const float4*)&xb[(size_t)row * FIN + k0 + kq];
        }
        #pragma unroll
        for (int v = 0; v < 4; v++) {
            int flat = t + 256 * v;
            int kr   = flat >> 5;
            int cq   = (flat & 31) * 4;
            *(float4*)&ws[kr][cq] = *(const float4*)&W[(size_t)(k0 + kr) * FOUT + cq];
        }
        __syncthreads();

        #pragma unroll
        for (int kk = 0; kk < 32; kk++) {
            const u64* wrow = (const u64*)&ws[kk][0];
            u64 bw0 = wrow[tc * 2];
            u64 bw1 = wrow[tc * 2 + 1];
            u64 bw2 = wrow[32 + tc * 2];
            u64 bw3 = wrow[32 + tc * 2 + 1];
            #pragma unroll
            for (int ri = 0; ri < 4; ri++) {
                float av = xs[r0 + ri][kk];
                u64 ap = pk2(av, av);
                fma2(acc[ri][0], ap, bw0);
                fma2(acc[ri][1], ap, bw1);
                fma2(acc[ri][2], ap, bw2);
                fma2(acc[ri][3], ap, bw3);
            }
        }
    }

    float* whb = g_Wh + ((size_t)b * Nn + i0) * FOUT;
    #pragma unroll
    for (int ri = 0; ri < 4; ri++) {
        float4 oa, ob;
        upk2(acc[ri][0], oa.x, oa.y); upk2(acc[ri][1], oa.z, oa.w);
        upk2(acc[ri][2], ob.x, ob.y); upk2(acc[ri][3], ob.z, ob.w);
        *(float4*)&whb[(size_t)(r0 + ri) * FOUT + c0a] = oa;
        *(float4*)&whb[(size_t)(r0 + ri) * FOUT + c0b] = ob;
    }
}

// ============================================================
// Kernel 2: f1[row] = Wh[row,:].a1 ; f2[row] = Wh[row,:].a2
// ============================================================
__global__ __launch_bounds__(128) void gat_calc_f(const float* __restrict__ a)
{
    const int row = blockIdx.x;
    const int t   = threadIdx.x;
    float wh = g_Wh[(size_t)row * FOUT + t];
    float p1 = wh * a[t];
    float p2 = wh * a[FOUT + t];
    #pragma unroll
    for (int o = 16; o > 0; o >>= 1) {
        p1 += __shfl_xor_sync(0xffffffffu, p1, o);
        p2 += __shfl_xor_sync(0xffffffffu, p2, o);
    }
    __shared__ float s1[4], s2[4];
    if ((t & 31) == 0) { s1[t >> 5] = p1; s2[t >> 5] = p2; }
    __syncthreads();
    if (t == 0) {
        g_f1[row] = s1[0] + s1[1] + s1[2] + s1[3];
        g_f2[row] = s2[0] + s2[1] + s2[2] + s2[3];
    }
}

// ============================================================
// Kernel 3: fused masked-leaky-softmax attention + P@Wh + ELU-out
// Block: 64 query rows x Fout=128, 256 threads, thread tile 4x8.
// P stored PRE-DUPLICATED as packed u64 (p,p): zero pack-MOVs in PV loop.
// Wh pairs read via LDS.64 directly into register pairs.
// ============================================================
__global__ __launch_bounds__(256, 2) void gat_attn(
    const int* __restrict__ adj, float* __restrict__ out)
{
    __shared__ __align__(16) float Whs[32][FOUT];   // 16 KB
    __shared__ __align__(16) u64  Ps2[64][33];      // 16.9 KB, (p,p) packed
    __shared__ float f1s[64];
    __shared__ float f2s[32];
    __shared__ float rowsum_s[64];

    const int t  = threadIdx.x;
    const int b  = blockIdx.y;
    const int i0 = blockIdx.x * 64;

    // PV mapping: 4 rows x 8 cols per thread (64 x 128 block tile)
    const int tr  = t >> 4;            // 0..15 -> rows tr*4..tr*4+3
    const int tc  = t & 15;
    const int r0  = tr * 4;

    // P mapping: warp rp handles rows rp+8k (k=0..7), col jp
    const int rp = t >> 5;             // 0..7
    const int jp = t & 31;

    if (t < 64) f1s[t] = g_f1[(size_t)b * Nn + i0 + t];

    u64 acc[4][4];
    #pragma unroll
    for (int i = 0; i < 4; i++)
        #pragma unroll
        for (int j = 0; j < 4; j++) acc[i][j] = pk2(0.f, 0.f);

    float sum_acc[8] = {0.f,0.f,0.f,0.f,0.f,0.f,0.f,0.f};

    const float* whb  = g_Wh + (size_t)b * Nn * FOUT;
    const int*   adjb = adj  + (size_t)b * Nn * Nn + jp;

    for (int jt = 0; jt < 64; jt++) {
        const int j0 = jt * 32;

        // prefetch adj (independent of smem) before barrier
        int av[8];
        #pragma unroll
        for (int k = 0; k < 8; k++)
            av[k] = adjb[(size_t)(i0 + rp + 8 * k) * Nn + j0];

        __syncthreads();   // previous PV done with Whs/Ps2

        // stage Wh tile [32][128]
        #pragma unroll
        for (int v = 0; v < 4; v++) {
            int flat = t + 256 * v;
            int jr   = flat >> 5;
            int cq   = (flat & 31) * 4;
            *(float4*)&Whs[jr][cq] = *(const float4*)&whb[(size_t)(j0 + jr) * FOUT + cq];
        }
        if (t < 32) f2s[t] = g_f2[(size_t)b * Nn + j0 + t];
        __syncthreads();

        // P tile: leaky -> mask -> exp (no max shift: overflow impossible)
        #pragma unroll
        for (int k = 0; k < 8; k++) {
            int r = rp + 8 * k;
            float e = f1s[r] + f2s[jp];
            e = (e < 0.f) ? 2.0f * e : e;          // ALPHA = 2.0
            float p = (av[k] > 0) ? __expf(e) : 0.f;
            Ps2[r][jp] = pk2(p, p);
            sum_acc[k] += p;
        }
        __syncthreads();

        // PV accumulate: 8 LDS.64 + 16 FMA2 per j, zero MOVs
        #pragma unroll 4
        for (int j = 0; j < 32; j++) {
            const u64* wrow = (const u64*)&Whs[j][0];
            u64 w0 = wrow[tc * 2];
            u64 w1 = wrow[tc * 2 + 1];
            u64 w2 = wrow[32 + tc * 2];
            u64 w3 = wrow[32 + tc * 2 + 1];
            #pragma unroll
            for (int ri = 0; ri < 4; ri++) {
                u64 pp = Ps2[r0 + ri][j];
                fma2(acc[ri][0], pp, w0);
                fma2(acc[ri][1], pp, w1);
                fma2(acc[ri][2], pp, w2);
                fma2(acc[ri][3], pp, w3);
            }
        }
    }

    // softmax denominators: warp rp owns rows {rp+8k}
    #pragma unroll
    for (int k = 0; k < 8; k++) {
        float s = sum_acc[k];
        #pragma unroll
        for (int o = 16; o > 0; o >>= 1)
            s += __shfl_xor_sync(0xffffffffu, s, o);
        if (jp == 0) rowsum_s[rp + 8 * k] = s;
    }
    __syncthreads();

    float* ob = out + ((size_t)b * Nn + i0) * FOUT;
    const int c0a = tc * 4;
    const int c0b = 64 + tc * 4;

    #pragma unroll
    for (int ri = 0; ri < 4; ri++) {
        float inv = 1.0f / rowsum_s[r0 + ri];
        float v[8];
        upk2(acc[ri][0], v[0], v[1]); upk2(acc[ri][1], v[2], v[3]);
        upk2(acc[ri][2], v[4], v[5]); upk2(acc[ri][3], v[6], v[7]);
        #pragma unroll
        for (int i = 0; i < 8; i++) {
            float h = v[i] * inv;
            v[i] = (h > 0.f) ? h : expm1f(h);
        }
        float4 oa  = make_float4(v[0], v[1], v[2], v[3]);
        float4 obv = make_float4(v[4], v[5], v[6], v[7]);
        *(float4*)&ob[(size_t)(r0 + ri) * FOUT + c0a] = oa;
        *(float4*)&ob[(size_t)(r0 + ri) * FOUT + c0b] = obv;
    }
}

// ============================================================
extern "C" void kernel_launch(void* const* d_in, const int* in_sizes, int n_in,
                              void* d_out, int out_size)
{
    const float* x   = (const float*)d_in[0];   // [8,2048,256] f32
    const int*   adj = (const int*)  d_in[1];   // [8,2048,2048] i32
    const float* W   = (const float*)d_in[2];   // [256,128] f32
    const float* a   = (const float*)d_in[3];   // [256,1] f32
    float*       out = (float*)d_out;           // [8,2048,128] f32

    dim3 g1(Nn / 64, Bb);
    gat_gemm_wh<<<g1, 256>>>(x, W);

    gat_calc_f<<<Bb * Nn, 128>>>(a);

    dim3 g3(Nn / 64, Bb);
    gat_attn<<<g3, 256>>>(adj, out);
}

// round 4
// speedup vs baseline: 2.4898x; 1.9722x over previous
#include <cuda_runtime.h>
#include <math.h>
#include <stdint.h>

#define Bb   8
#define Nn   2048
#define FIN  256
#define FOUT 128
#define CH   32          // j-chunk
#define NCH  (Nn / CH)   // 64

typedef unsigned long long u64;
typedef unsigned int u32;

// Scratch (device globals: allocation-free rule)
__device__ float g_WhT[Bb * FOUT * Nn];   // [b][f][j], tf32-rounded fp32 bits
__device__ float g_f1[Bb * Nn];
__device__ float g_f2[Bb * Nn];

// ---------------- helpers ----------------
__forceinline__ __device__ u64 pk2(float lo, float hi) {
    u64 r; asm("mov.b64 %0,{%1,%2};" : "=l"(r) : "f"(lo), "f"(hi)); return r;
}
__forceinline__ __device__ void upk2(u64 v, float &lo, float &hi) {
    asm("mov.b64 {%0,%1},%2;" : "=f"(lo), "=f"(hi) : "l"(v));
}
__forceinline__ __device__ void fma2(u64 &d, u64 a, u64 b) {
    asm("fma.rn.f32x2 %0,%1,%2,%3;" : "=l"(d) : "l"(a), "l"(b), "l"(d));
}
__forceinline__ __device__ u32 tf32r(float f) {
    u32 r; asm("cvt.rna.tf32.f32 %0,%1;" : "=r"(r) : "f"(f)); return r;
}
// m16n8k8 tf32 MMA (legacy tensor path; plain compute_80+ feature)
__forceinline__ __device__ void mma168(float* d, const u32* a, const u32* b) {
    asm volatile(
        "mma.sync.aligned.m16n8k8.row.col.f32.tf32.tf32.f32 "
        "{%0,%1,%2,%3},{%4,%5,%6,%7},{%8,%9},{%0,%1,%2,%3};"
        : "+f"(d[0]), "+f"(d[1]), "+f"(d[2]), "+f"(d[3])
        : "r"(a[0]), "r"(a[1]), "r"(a[2]), "r"(a[3]), "r"(b[0]), "r"(b[1]));
}

// ============================================================
// Kernel 1: Wh = x@W (fp32 scalar), fused f1/f2 epilogue,
// writes WhT[b][f][j] (tf32-rounded) via smem transpose.
// BM=32, BN=128, BK=32, 256 threads, thread tile 2x8.
// ============================================================
__global__ __launch_bounds__(256) void gat_gemm_wh(
    const float* __restrict__ x, const float* __restrict__ W,
    const float* __restrict__ a)
{
    __shared__ __align__(16) float xs[32][32];
    __shared__ __align__(16) float ws[32][FOUT];
    __shared__ __align__(16) float trans[32][129];
    __shared__ float a_s[2 * FOUT];

    const int t  = threadIdx.x;
    const int b  = blockIdx.y;
    const int i0 = blockIdx.x * 32;
    const int tr = t >> 4, tc = t & 15;
    const int r0 = tr * 2, c0a = tc * 4, c0b = 64 + tc * 4;

    a_s[t] = a[t];

    u64 acc[2][4];
    #pragma unroll
    for (int i = 0; i < 2; i++)
        #pragma unroll
        for (int j = 0; j < 4; j++) acc[i][j] = pk2(0.f, 0.f);

    const float* xb = x + ((size_t)b * Nn + i0) * FIN;

    const int xrow = t >> 3, xkq = (t & 7) * 4;
    float4 rx = *(const float4*)&xb[(size_t)xrow * FIN + xkq];
    float4 rw[4];
    #pragma unroll
    for (int v = 0; v < 4; v++) {
        int flat = t + 256 * v;
        rw[v] = *(const float4*)&W[(size_t)(flat >> 5) * FOUT + (flat & 31) * 4];
    }

    for (int kt = 0; kt < 8; kt++) {
        if (kt > 0) __syncthreads();
        *(float4*)&xs[xrow][xkq] = rx;
        #pragma unroll
        for (int v = 0; v < 4; v++) {
            int flat = t + 256 * v;
            *(float4*)&ws[flat >> 5][(flat & 31) * 4] = rw[v];
        }
        __syncthreads();
        if (kt < 7) {
            int k0 = (kt + 1) * 32;
            rx = *(const float4*)&xb[(size_t)xrow * FIN + k0 + xkq];
            #pragma unroll
            for (int v = 0; v < 4; v++) {
                int flat = t + 256 * v;
                rw[v] = *(const float4*)&W[(size_t)(k0 + (flat >> 5)) * FOUT + (flat & 31) * 4];
            }
        }
        #pragma unroll
        for (int kk = 0; kk < 32; kk++) {
            const u64* wrow = (const u64*)&ws[kk][0];
            u64 w0 = wrow[tc * 2], w1 = wrow[tc * 2 + 1];
            u64 w2 = wrow[32 + tc * 2], w3 = wrow[32 + tc * 2 + 1];
            #pragma unroll
            for (int ri = 0; ri < 2; ri++) {
                float av = xs[r0 + ri][kk];
                u64 ap = pk2(av, av);
                fma2(acc[ri][0], ap, w0);
                fma2(acc[ri][1], ap, w1);
                fma2(acc[ri][2], ap, w2);
                fma2(acc[ri][3], ap, w3);
            }
        }
    }

    float v[2][8];
    #pragma unroll
    for (int ri = 0; ri < 2; ri++) {
        upk2(acc[ri][0], v[ri][0], v[ri][1]); upk2(acc[ri][1], v[ri][2], v[ri][3]);
        upk2(acc[ri][2], v[ri][4], v[ri][5]); upk2(acc[ri][3], v[ri][6], v[ri][7]);
    }

    #pragma unroll
    for (int ri = 0; ri < 2; ri++) {
        float p1 = 0.f, p2 = 0.f;
        #pragma unroll
        for (int u = 0; u < 4; u++) {
            p1 += v[ri][u] * a_s[c0a + u] + v[ri][4 + u] * a_s[c0b + u];
            p2 += v[ri][u] * a_s[FOUT + c0a + u] + v[ri][4 + u] * a_s[FOUT + c0b + u];
        }
        #pragma unroll
        for (int o = 8; o > 0; o >>= 1) {
            p1 += __shfl_xor_sync(0xffffffffu, p1, o);
            p2 += __shfl_xor_sync(0xffffffffu, p2, o);
        }
        if (tc == 0) {
            g_f1[(size_t)b * Nn + i0 + r0 + ri] = p1;
            g_f2[(size_t)b * Nn + i0 + r0 + ri] = p2;
        }
        #pragma unroll
        for (int u = 0; u < 4; u++) {
            trans[r0 + ri][c0a + u] = v[ri][u];
            trans[r0 + ri][c0b + u] = v[ri][4 + u];
        }
    }
    __syncthreads();

    const int f  = t >> 1;
    const int jp = t & 1;
    float* wtrow = g_WhT + ((size_t)(b * FOUT + f)) * Nn + i0 + jp * 16;
    #pragma unroll
    for (int q = 0; q < 4; q++) {
        uint4 pv;
        pv.x = tf32r(trans[jp * 16 + q * 4 + 0][f]);
        pv.y = tf32r(trans[jp * 16 + q * 4 + 1][f]);
        pv.z = tf32r(trans[jp * 16 + q * 4 + 2][f]);
        pv.w = tf32r(trans[jp * 16 + q * 4 + 3][f]);
        *(uint4*)&wtrow[q * 4] = pv;
    }
}

// ============================================================
// Kernel 2: fused attention, mma.sync m16n8k8 tf32.
// CTA tile: 128 i x 128 f. 8 warps: wr=wid&3 (32 i), wc=wid>>2 (64 f).
// j chunks of 32, double-buffered swizzled smem for P (A) and WhT (B).
// ============================================================
#define SM_PS   0                      // 2 * 128*32*4 = 32768
#define SM_WHS  32768                  // 32768
#define SM_F2   65536                  // 8192
#define SM_RS   73728                  // 512
#define SM_TOT  74240

__global__ __launch_bounds__(256, 1) void gat_attn(
    const int* __restrict__ adj, float* __restrict__ out)
{
    extern __shared__ __align__(16) char dsm[];
    u32*   Ps   = (u32*)(dsm + SM_PS);
    u32*   Whs  = (u32*)(dsm + SM_WHS);
    float* f2s  = (float*)(dsm + SM_F2);
    float* rows = (float*)(dsm + SM_RS);

    const int t    = threadIdx.x;
    const int lane = t & 31;
    const int wid  = t >> 5;
    const int wr   = wid & 3;
    const int wc   = wid >> 2;
    const int g    = lane >> 2;      // groupID
    const int cl   = lane & 3;       // threadID_in_group
    const int b    = blockIdx.y;
    const int i0   = blockIdx.x * 128;

    // builder mapping: row i = t>>1, 16 j's starting at jh
    const int i  = t >> 1;
    const int jh = (t & 1) * 16;
    const u32 psw = ((u32)(i & 7)) << 2;

    const float f1v  = g_f1[(size_t)b * Nn + i0 + i];
    const int*   arow = adj   + ((size_t)(b * Nn + i0 + i)) * Nn + jh;
    const float* wrow = g_WhT + ((size_t)(b * FOUT + i)) * Nn + jh;
    const float* f2g  = g_f2  + (size_t)b * Nn;

    float acc[2][8][4];
    #pragma unroll
    for (int mt = 0; mt < 2; mt++)
        #pragma unroll
        for (int nt = 0; nt < 8; nt++)
            #pragma unroll
            for (int e = 0; e < 4; e++) acc[mt][nt][e] = 0.f;

    // stage f2 (whole batch row: 2048 floats)
    #pragma unroll
    for (int q = 0; q < 2; q++) {
        int idx = (t + 256 * q) * 4;
        *(float4*)&f2s[idx] = *(const float4*)&f2g[idx];
    }

    int4  sav[4];
    uint4 swv[4];
    float rs = 0.f;

    // ---- issue LDGs for chunk c into regs ----
    #define ISSUE(c_) do {                                             \
        const int _j0 = (c_) * CH;                                     \
        _Pragma("unroll")                                              \
        for (int q = 0; q < 4; q++) {                                  \
            sav[q] = *(const int4*)&arow[_j0 + q * 4];                 \
            swv[q] = *(const uint4*)&wrow[_j0 + q * 4];                \
        }                                                              \
    } while (0)

    // ---- finish chunk c into buffer buf ----
    #define FINISH(c_, buf_) do {                                      \
        const int _j0 = (c_) * CH;                                     \
        u32* _P = Ps  + (buf_) * 4096;                                 \
        u32* _W = Whs + (buf_) * 4096;                                 \
        _Pragma("unroll")                                              \
        for (int q = 0; q < 4; q++) {                                  \
            float4 f2v = *(const float4*)&f2s[_j0 + jh + q * 4];       \
            int4 av = sav[q];                                          \
            float e0 = f1v + f2v.x; e0 = (e0 < 0.f) ? 2.f * e0 : e0;   \
            float e1 = f1v + f2v.y; e1 = (e1 < 0.f) ? 2.f * e1 : e1;   \
            float e2 = f1v + f2v.z; e2 = (e2 < 0.f) ? 2.f * e2 : e2;   \
            float e3 = f1v + f2v.w; e3 = (e3 < 0.f) ? 2.f * e3 : e3;   \
            float p0 = (av.x > 0) ? __expf(e0) : 0.f;                  \
            float p1 = (av.y > 0) ? __expf(e1) : 0.f;                  \
            float p2 = (av.z > 0) ? __expf(e2) : 0.f;                  \
            float p3 = (av.w > 0) ? __expf(e3) : 0.f;                  \
            uint4 pv;                                                  \
            pv.x = tf32r(p0); pv.y = tf32r(p1);                        \
            pv.z = tf32r(p2); pv.w = tf32r(p3);                        \
            rs += __uint_as_float(pv.x) + __uint_as_float(pv.y)        \
                + __uint_as_float(pv.z) + __uint_as_float(pv.w);       \
            u32 sidx = (u32)(i * 32) + (((u32)(jh + q * 4)) ^ psw);    \
            *(uint4*)&_P[sidx] = pv;                                   \
            *(uint4*)&_W[sidx] = swv[q];                               \
        }                                                              \
    } while (0)

    // prologue
    ISSUE(0);
    __syncthreads();          // f2s visible
    FINISH(0, 0);
    __syncthreads();          // buf0 visible

    for (int c = 0; c < NCH; c++) {
        const int s = c & 1;
        if (c < NCH - 1) ISSUE(c + 1);

        // MMA on buffer s
        {
            const u32* P = Ps  + s * 4096;
            const u32* Wb = Whs + s * 4096;
            const u32 sw = ((u32)g) << 2;
            #pragma unroll
            for (int ks = 0; ks < 4; ks++) {
                const int kc = ks * 8 + cl;
                u32 afr[2][4];
                #pragma unroll
                for (int mt = 0; mt < 2; mt++) {
                    int r = wr * 32 + mt * 16 + g;
                    afr[mt][0] = P[r * 32 + ((u32)kc ^ sw)];
                    afr[mt][1] = P[(r + 8) * 32 + ((u32)kc ^ sw)];
                    afr[mt][2] = P[r * 32 + ((u32)(kc + 4) ^ sw)];
                    afr[mt][3] = P[(r + 8) * 32 + ((u32)(kc + 4) ^ sw)];
                }
                #pragma unroll
                for (int nt = 0; nt < 8; nt++) {
                    int n = wc * 64 + nt * 8 + g;
                    u32 bfr[2];
                    bfr[0] = Wb[n * 32 + ((u32)kc ^ sw)];
                    bfr[1] = Wb[n * 32 + ((u32)(kc + 4) ^ sw)];
                    mma168(acc[0][nt], afr[0], bfr);
                    mma168(acc[1][nt], afr[1], bfr);
                }
            }
        }

        if (c < NCH - 1) FINISH(c + 1, s ^ 1);
        __syncthreads();
    }

    // rowsum: threads t and t^1 share builder row i
    rs += __shfl_xor_sync(0xffffffffu, rs, 1);
    if ((t & 1) == 0) rows[i] = rs;
    __syncthreads();

    // epilogue
    #pragma unroll
    for (int mt = 0; mt < 2; mt++) {
        #pragma unroll
        for (int h = 0; h < 2; h++) {
            const int row = wr * 32 + mt * 16 + g + h * 8;
            const float inv = 1.0f / rows[row];
            float* orow = out + ((size_t)(b * Nn + i0 + row)) * FOUT + wc * 64 + cl * 2;
            #pragma unroll
            for (int nt = 0; nt < 8; nt++) {
                float h0 = acc[mt][nt][h * 2 + 0] * inv;
                float h1 = acc[mt][nt][h * 2 + 1] * inv;
                h0 = (h0 > 0.f) ? h0 : expm1f(h0);
                h1 = (h1 > 0.f) ? h1 : expm1f(h1);
                float2 o = make_float2(h0, h1);
                *(float2*)&orow[nt * 8] = o;
            }
        }
    }
}

// ============================================================
extern "C" void kernel_launch(void* const* d_in, const int* in_sizes, int n_in,
                              void* d_out, int out_size)
{
    const float* x   = (const float*)d_in[0];   // [8,2048,256] f32
    const int*   adj = (const int*)  d_in[1];   // [8,2048,2048] i32
    const float* W   = (const float*)d_in[2];   // [256,128] f32
    const float* a   = (const float*)d_in[3];   // [256,1] f32
    float*       out = (float*)d_out;           // [8,2048,128] f32

    dim3 g1(Nn / 32, Bb);
    gat_gemm_wh<<<g1, 256>>>(x, W, a);

    static int smem_set = 0;
    if (!smem_set) {
        cudaFuncSetAttribute(gat_attn, cudaFuncAttributeMaxDynamicSharedMemorySize, SM_TOT);
        smem_set = 1;
    }
    dim3 g2(Nn / 128, Bb);
    gat_attn<<<g2, 256, SM_TOT>>>(adj, out);
}

// round 5
// speedup vs baseline: 2.4965x; 1.0027x over previous
#include <cuda_runtime.h>
#include <math.h>
#include <stdint.h>

#define Bb   8
#define Nn   2048
#define FIN  256
#define FOUT 128
#define CH   32          // j-chunk
#define NCH  (Nn / CH)   // 64

typedef unsigned long long u64;
typedef unsigned int u32;

// Scratch (device globals: allocation-free rule)
__device__ float  g_WhT[Bb * FOUT * Nn];    // [b][f][j], tf32-rounded bits
__device__ float4 g_ipack[Bb * Nn];         // (f1, exp(f1), exp(2 f1), 0)
__device__ float4 g_jpack[Bb * Nn];         // (f2, exp(f2), exp(2 f2), 0)

// ---------------- helpers ----------------
__forceinline__ __device__ u64 pk2(float lo, float hi) {
    u64 r; asm("mov.b64 %0,{%1,%2};" : "=l"(r) : "f"(lo), "f"(hi)); return r;
}
__forceinline__ __device__ void upk2(u64 v, float &lo, float &hi) {
    asm("mov.b64 {%0,%1},%2;" : "=f"(lo), "=f"(hi) : "l"(v));
}
__forceinline__ __device__ void fma2(u64 &d, u64 a, u64 b) {
    asm("fma.rn.f32x2 %0,%1,%2,%3;" : "=l"(d) : "l"(a), "l"(b), "l"(d));
}
__forceinline__ __device__ u32 tf32r(float f) {
    u32 r; asm("cvt.rna.tf32.f32 %0,%1;" : "=r"(r) : "f"(f)); return r;
}
__forceinline__ __device__ u32 smem_u32(const void* p) {
    u32 a;
    asm("{ .reg .u64 t; cvta.to.shared.u64 t,%1; cvt.u32.u64 %0,t; }" : "=r"(a) : "l"(p));
    return a;
}
// m16n8k8 tf32 MMA (legacy tensor path; compute_80+ feature, no 'a' suffix needed)
__forceinline__ __device__ void mma168(float* d, const u32* a, const u32* b) {
    asm volatile(
        "mma.sync.aligned.m16n8k8.row.col.f32.tf32.tf32.f32 "
        "{%0,%1,%2,%3},{%4,%5,%6,%7},{%8,%9},{%0,%1,%2,%3};"
        : "+f"(d[0]), "+f"(d[1]), "+f"(d[2]), "+f"(d[3])
        : "r"(a[0]), "r"(a[1]), "r"(a[2]), "r"(a[3]), "r"(b[0]), "r"(b[1]));
}
#define CP_ASYNC16(sdst, gsrc) \
    asm volatile("cp.async.cg.shared.global [%0], [%1], 16;" :: "r"(sdst), "l"(gsrc))
#define CP_COMMIT()  asm volatile("cp.async.commit_group;" ::: "memory")
#define CP_WAIT0()   asm volatile("cp.async.wait_group 0;" ::: "memory")

// ============================================================
// Kernel 1: Wh = x@W (fp32 scalar, BM=64), fused epilogue:
//   f1/f2 per row -> g_ipack/g_jpack (with precomputed exps),
//   WhT[b][f][j] (tf32-rounded) via smem transpose.
// ============================================================
__global__ __launch_bounds__(256) void gat_gemm_wh(
    const float* __restrict__ x, const float* __restrict__ W,
    const float* __restrict__ a)
{
    __shared__ __align__(16) char arena[64 * 129 * 4 + 64];   // 33 KB (aliased)
    __shared__ float a_s[2 * FOUT];
    float (*xs)[32]    = (float(*)[32])arena;                 // 64x32 (8 KB)
    float (*ws)[FOUT]  = (float(*)[FOUT])(arena + 8192);      // 32x128 (16 KB)
    float (*trans)[129] = (float(*)[129])arena;               // 64x129 (reuse)

    const int t  = threadIdx.x;
    const int b  = blockIdx.y;
    const int i0 = blockIdx.x * 64;
    const int tr = t >> 4, tc = t & 15;
    const int r0 = tr * 4, c0a = tc * 4, c0b = 64 + tc * 4;

    a_s[t] = a[t];

    u64 acc[4][4];
    #pragma unroll
    for (int i = 0; i < 4; i++)
        #pragma unroll
        for (int j = 0; j < 4; j++) acc[i][j] = pk2(0.f, 0.f);

    const float* xb = x + ((size_t)b * Nn + i0) * FIN;

    float4 rx[2], rw[4];
    #pragma unroll
    for (int v = 0; v < 2; v++) {
        int flat = t + 256 * v;
        rx[v] = *(const float4*)&xb[(size_t)(flat >> 3) * FIN + (flat & 7) * 4];
    }
    #pragma unroll
    for (int v = 0; v < 4; v++) {
        int flat = t + 256 * v;
        rw[v] = *(const float4*)&W[(size_t)(flat >> 5) * FOUT + (flat & 31) * 4];
    }

    for (int kt = 0; kt < 8; kt++) {
        if (kt > 0) __syncthreads();
        #pragma unroll
        for (int v = 0; v < 2; v++) {
            int flat = t + 256 * v;
            *(float4*)&xs[flat >> 3][(flat & 7) * 4] = rx[v];
        }
        #pragma unroll
        for (int v = 0; v < 4; v++) {
            int flat = t + 256 * v;
            *(float4*)&ws[flat >> 5][(flat & 31) * 4] = rw[v];
        }
        __syncthreads();
        if (kt < 7) {
            int k0 = (kt + 1) * 32;
            #pragma unroll
            for (int v = 0; v < 2; v++) {
                int flat = t + 256 * v;
                rx[v] = *(const float4*)&xb[(size_t)(flat >> 3) * FIN + k0 + (flat & 7) * 4];
            }
            #pragma unroll
            for (int v = 0; v < 4; v++) {
                int flat = t + 256 * v;
                rw[v] = *(const float4*)&W[(size_t)(k0 + (flat >> 5)) * FOUT + (flat & 31) * 4];
            }
        }
        #pragma unroll
        for (int kk = 0; kk < 32; kk++) {
            const u64* wrow = (const u64*)&ws[kk][0];
            u64 w0 = wrow[tc * 2], w1 = wrow[tc * 2 + 1];
            u64 w2 = wrow[32 + tc * 2], w3 = wrow[32 + tc * 2 + 1];
            #pragma unroll
            for (int ri = 0; ri < 4; ri++) {
                float av = xs[r0 + ri][kk];
                u64 ap = pk2(av, av);
                fma2(acc[ri][0], ap, w0);
                fma2(acc[ri][1], ap, w1);
                fma2(acc[ri][2], ap, w2);
                fma2(acc[ri][3], ap, w3);
            }
        }
    }

    float v[4][8];
    #pragma unroll
    for (int ri = 0; ri < 4; ri++) {
        upk2(acc[ri][0], v[ri][0], v[ri][1]); upk2(acc[ri][1], v[ri][2], v[ri][3]);
        upk2(acc[ri][2], v[ri][4], v[ri][5]); upk2(acc[ri][3], v[ri][6], v[ri][7]);
    }

    __syncthreads();   // done with xs/ws; arena becomes trans

    #pragma unroll
    for (int ri = 0; ri < 4; ri++) {
        float p1 = 0.f, p2 = 0.f;
        #pragma unroll
        for (int u = 0; u < 4; u++) {
            p1 += v[ri][u] * a_s[c0a + u] + v[ri][4 + u] * a_s[c0b + u];
            p2 += v[ri][u] * a_s[FOUT + c0a + u] + v[ri][4 + u] * a_s[FOUT + c0b + u];
        }
        #pragma unroll
        for (int o = 8; o > 0; o >>= 1) {
            p1 += __shfl_xor_sync(0xffffffffu, p1, o);
            p2 += __shfl_xor_sync(0xffffffffu, p2, o);
        }
        if (tc == 0) {
            size_t row = (size_t)b * Nn + i0 + r0 + ri;
            g_ipack[row] = make_float4(p1, __expf(p1), __expf(2.f * p1), 0.f);
            g_jpack[row] = make_float4(p2, __expf(p2), __expf(2.f * p2), 0.f);
        }
        #pragma unroll
        for (int u = 0; u < 4; u++) {
            trans[r0 + ri][c0a + u] = v[ri][u];
            trans[r0 + ri][c0b + u] = v[ri][4 + u];
        }
    }
    __syncthreads();

    const int f  = t >> 1;
    const int jp = t & 1;
    float* wtrow = g_WhT + ((size_t)(b * FOUT + f)) * Nn + i0 + jp * 32;
    #pragma unroll
    for (int q = 0; q < 8; q++) {
        uint4 pv;
        pv.x = tf32r(trans[jp * 32 + q * 4 + 0][f]);
        pv.y = tf32r(trans[jp * 32 + q * 4 + 1][f]);
        pv.z = tf32r(trans[jp * 32 + q * 4 + 2][f]);
        pv.w = tf32r(trans[jp * 32 + q * 4 + 3][f]);
        *(uint4*)&wtrow[q * 4] = pv;
    }
}

// ============================================================
// Kernel 2: fused attention, mma.sync m16n8k8 tf32, exp-free builder.
// CTA: 64 i x 128 f, 8 warps (wr=wid&1: 32-row half, wc=wid>>1: 32-col grp).
// P built from precomputed exp factors; WhT staged via cp.async.
// ============================================================
#define SM_PS   0                        // 2 * 64*32*4   = 16384
#define SM_WS   16384                    // 2 * 128*32*4  = 32768
#define SM_JP   49152                    // 2048 float4   = 32768
#define SM_RS   81920                    // 64 floats
#define SM_TOT  82240

__global__ __launch_bounds__(256, 2) void gat_attn(
    const int* __restrict__ adj, float* __restrict__ out)
{
    extern __shared__ __align__(16) char dsm[];
    u32*    Ps     = (u32*)(dsm + SM_PS);
    u32*    Whs    = (u32*)(dsm + SM_WS);
    float4* jpackS = (float4*)(dsm + SM_JP);
    float*  rows   = (float*)(dsm + SM_RS);
    const u32 sb = smem_u32(dsm);

    const int t    = threadIdx.x;
    const int lane = t & 31;
    const int wid  = t >> 5;
    const int wr   = wid & 1;
    const int wc   = wid >> 1;
    const int g    = lane >> 2;
    const int cl   = lane & 3;
    const int b    = blockIdx.y;
    const int i0   = blockIdx.x * 64;

    // builder mapping: row iL = t>>2, 8 j's starting at jh
    const int iL = t >> 2;
    const int jh = (t & 3) * 8;
    const u32 psw = ((u32)(iL & 7)) << 2;

    const float4 ip = g_ipack[(size_t)b * Nn + i0 + iL];
    const float thr = -ip.x, c1 = ip.y, c2 = ip.z;
    const int*    arow  = adj    + ((size_t)(b * Nn + i0 + iL)) * Nn + jh;
    const float*  whtb  = g_WhT  + (size_t)b * FOUT * Nn;
    const float4* jpg   = g_jpack + (size_t)b * Nn;

    float acc[2][4][4];
    #pragma unroll
    for (int mt = 0; mt < 2; mt++)
        #pragma unroll
        for (int nt = 0; nt < 4; nt++)
            #pragma unroll
            for (int e = 0; e < 4; e++) acc[mt][nt][e] = 0.f;

    int4  sav[2];
    float rs = 0.f;

    // stage jpack (whole batch row)
    #pragma unroll
    for (int q = 0; q < 8; q++) {
        int idx = t + 256 * q;
        jpackS[idx] = jpg[idx];
    }

    #define ISSUE_ADJ(c_) do {                                          \
        const int _j0 = (c_) * CH;                                      \
        sav[0] = *(const int4*)&arow[_j0];                              \
        sav[1] = *(const int4*)&arow[_j0 + 4];                          \
    } while (0)

    // cp.async next W chunk into buffer buf
    #define ISSUE_W(c_, buf_) do {                                      \
        const int _j0 = (c_) * CH;                                      \
        const u32 _wb = sb + SM_WS + (buf_) * 16384;                    \
        _Pragma("unroll")                                               \
        for (int q = 0; q < 4; q++) {                                   \
            int flat = t + 256 * q;                                     \
            int row  = flat >> 3;                                       \
            int jq   = (flat & 7) * 4;                                  \
            u32 sidx = (u32)(row * 32) + ((u32)jq ^ (((u32)(row & 7)) << 2)); \
            CP_ASYNC16(_wb + (sidx << 2),                               \
                       &whtb[(size_t)row * Nn + _j0 + jq]);             \
        }                                                               \
        CP_COMMIT();                                                    \
    } while (0)

    #define FINISH(c_, buf_) do {                                       \
        const int _j0 = (c_) * CH;                                      \
        u32* _P = Ps + (buf_) * 2048;                                   \
        _Pragma("unroll")                                               \
        for (int q = 0; q < 2; q++) {                                   \
            const int* _a = (const int*)&sav[q];                        \
            uint4 pv;                                                   \
            u32*  pw = (u32*)&pv;                                       \
            _Pragma("unroll")                                           \
            for (int u = 0; u < 4; u++) {                               \
                float4 jp2 = jpackS[_j0 + jh + q * 4 + u];              \
                float p = (jp2.x >= thr) ? c1 * jp2.y : c2 * jp2.z;     \
                p = (_a[u] > 0) ? p : 0.f;                              \
                pw[u] = tf32r(p);                                       \
                rs += __uint_as_float(pw[u]);                           \
            }                                                           \
            *(uint4*)&_P[iL * 32 + (((u32)(jh + q * 4)) ^ psw)] = pv;   \
        }                                                               \
    } while (0)

    // prologue: chunk 0
    ISSUE_W(0, 0);
    ISSUE_ADJ(0);
    __syncthreads();            // jpackS visible
    FINISH(0, 0);
    CP_WAIT0();
    __syncthreads();            // buf0 (P and W) visible

    for (int c = 0; c < NCH; c++) {
        const int s = c & 1;
        if (c < NCH - 1) { ISSUE_ADJ(c + 1); ISSUE_W(c + 1, s ^ 1); }

        // MMA on buffer s
        {
            const u32* P  = Ps  + s * 2048;
            const u32* Wb = Whs + s * 4096;
            const u32 sw = ((u32)g) << 2;
            #pragma unroll
            for (int ks = 0; ks < 4; ks++) {
                const int kc = ks * 8 + cl;
                u32 afr[2][4];
                #pragma unroll
                for (int mt = 0; mt < 2; mt++) {
                    int r = wr * 32 + mt * 16 + g;
                    afr[mt][0] = P[r * 32 + ((u32)kc ^ sw)];
                    afr[mt][1] = P[(r + 8) * 32 + ((u32)kc ^ sw)];
                    afr[mt][2] = P[r * 32 + ((u32)(kc + 4) ^ sw)];
                    afr[mt][3] = P[(r + 8) * 32 + ((u32)(kc + 4) ^ sw)];
                }
                #pragma unroll
                for (int nt = 0; nt < 4; nt++) {
                    int n = wc * 32 + nt * 8 + g;
                    u32 bfr[2];
                    bfr[0] = Wb[n * 32 + ((u32)kc ^ sw)];
                    bfr[1] = Wb[n * 32 + ((u32)(kc + 4) ^ sw)];
                    mma168(acc[0][nt], afr[0], bfr);
                    mma168(acc[1][nt], afr[1], bfr);
                }
            }
        }

        if (c < NCH - 1) { FINISH(c + 1, s ^ 1); CP_WAIT0(); }
        __syncthreads();
    }

    // rowsum: threads t..t|3 share builder row iL
    rs += __shfl_xor_sync(0xffffffffu, rs, 1);
    rs += __shfl_xor_sync(0xffffffffu, rs, 2);
    if ((t & 3) == 0) rows[iL] = rs;
    __syncthreads();

    // epilogue
    #pragma unroll
    for (int mt = 0; mt < 2; mt++) {
        #pragma unroll
        for (int h = 0; h < 2; h++) {
            const int row = wr * 32 + mt * 16 + g + h * 8;
            const float inv = 1.0f / rows[row];
            float* orow = out + ((size_t)(b * Nn + i0 + row)) * FOUT + wc * 32 + cl * 2;
            #pragma unroll
            for (int nt = 0; nt < 4; nt++) {
                float h0 = acc[mt][nt][h * 2 + 0] * inv;
                float h1 = acc[mt][nt][h * 2 + 1] * inv;
                h0 = (h0 > 0.f) ? h0 : expm1f(h0);
                h1 = (h1 > 0.f) ? h1 : expm1f(h1);
                float2 o = make_float2(h0, h1);
                *(float2*)&orow[nt * 8] = o;
            }
        }
    }
}

// ============================================================
extern "C" void kernel_launch(void* const* d_in, const int* in_sizes, int n_in,
                              void* d_out, int out_size)
{
    const float* x   = (const float*)d_in[0];   // [8,2048,256] f32
    const int*   adj = (const int*)  d_in[1];   // [8,2048,2048] i32
    const float* W   = (const float*)d_in[2];   // [256,128] f32
    const float* a   = (const float*)d_in[3];   // [256,1] f32
    float*       out = (float*)d_out;           // [8,2048,128] f32

    dim3 g1(Nn / 64, Bb);
    gat_gemm_wh<<<g1, 256>>>(x, W, a);

    cudaFuncSetAttribute(gat_attn, cudaFuncAttributeMaxDynamicSharedMemorySize, SM_TOT);
    dim3 g2(Nn / 64, Bb);
    gat_attn<<<g2, 256, SM_TOT>>>(adj, out);
}